// round 2
// baseline (speedup 1.0000x reference)
#include <cuda_runtime.h>
#include <cstdint>

// Problem constants (fixed by the dataset)
#define NTOK 2048          // B*T
#define DDIM 1024
#define EXP  16
#define FF   512
#define FSH  2048
#define PAIRS (NTOK*2)

// ---------------- scratch (device globals: no allocations allowed) ----------
__device__ float g_probs[NTOK * EXP];
__device__ float g_topkw[PAIRS];
__device__ int   g_topki[PAIRS];
__device__ float g_sgate[NTOK];
__device__ int   g_count[EXP];
__device__ int   g_offset[EXP];
__device__ int   g_cursor[EXP];
__device__ int   g_perm[PAIRS];
__device__ float g_gu  [(size_t)PAIRS * 1024];   // expert gate/up raw accum
__device__ float g_h   [(size_t)PAIRS * FF];     // expert hidden
__device__ float g_y   [(size_t)PAIRS * DDIM];   // weighted expert outputs
__device__ float g_sraw[(size_t)NTOK * 2 * FSH]; // shared gate/up raw accum
__device__ float g_s   [(size_t)NTOK * FSH];     // shared hidden
__device__ float g_sh  [(size_t)NTOK * DDIM];    // shared output

// ---------------- small kernels --------------------------------------------
__global__ void k_zero() {
    int i = threadIdx.x;
    if (i < EXP) g_count[i] = 0;
}

// one warp per token: router logits, softmax, top-2, shared-gate scalar
__global__ void k_router(const float* __restrict__ x,
                         const float* __restrict__ rw,
                         const float* __restrict__ sgw) {
    int t    = blockIdx.x * 4 + (threadIdx.x >> 5);
    int lane = threadIdx.x & 31;
    if (t >= NTOK) return;
    const float* xr = x + (size_t)t * DDIM;

    float acc[EXP];
#pragma unroll
    for (int e = 0; e < EXP; e++) acc[e] = 0.f;
    float sg = 0.f;

    for (int j = lane; j < DDIM; j += 32) {
        float xv = xr[j];
        const float* r = rw + (size_t)j * EXP;
#pragma unroll
        for (int e = 0; e < EXP; e++) acc[e] = fmaf(xv, r[e], acc[e]);
        sg = fmaf(xv, sgw[j], sg);
    }
#pragma unroll
    for (int off = 16; off; off >>= 1) {
#pragma unroll
        for (int e = 0; e < EXP; e++) acc[e] += __shfl_xor_sync(0xffffffffu, acc[e], off);
        sg += __shfl_xor_sync(0xffffffffu, sg, off);
    }
    float mx = acc[0];
#pragma unroll
    for (int e = 1; e < EXP; e++) mx = fmaxf(mx, acc[e]);
    float pr[EXP]; float sum = 0.f;
#pragma unroll
    for (int e = 0; e < EXP; e++) { pr[e] = __expf(acc[e] - mx); sum += pr[e]; }
    float inv = 1.f / sum;
#pragma unroll
    for (int e = 0; e < EXP; e++) pr[e] *= inv;

    if (lane < EXP) g_probs[(size_t)t * EXP + lane] = pr[lane];

    if (lane == 0) {
        int i1 = 0; float p1 = pr[0];
#pragma unroll
        for (int e = 1; e < EXP; e++) if (pr[e] > p1) { p1 = pr[e]; i1 = e; }
        int i2 = (i1 == 0) ? 1 : 0; float p2 = pr[i2];
#pragma unroll
        for (int e = 0; e < EXP; e++)
            if (e != i1 && pr[e] > p2) { p2 = pr[e]; i2 = e; }
        float s2 = p1 + p2; if (s2 < 1e-9f) s2 = 1e-9f;
        g_topkw[t * 2 + 0] = p1 / s2;
        g_topkw[t * 2 + 1] = p2 / s2;
        g_topki[t * 2 + 0] = i1;
        g_topki[t * 2 + 1] = i2;
        atomicAdd(&g_count[i1], 1);
        atomicAdd(&g_count[i2], 1);
        g_sgate[t] = 1.f / (1.f + __expf(-sg));
    }
}

__global__ void k_scan() {
    int s = 0;
    for (int e = 0; e < EXP; e++) { g_offset[e] = s; g_cursor[e] = s; s += g_count[e]; }
}

__global__ void k_scatter() {
    int p = blockIdx.x * 256 + threadIdx.x;
    if (p >= PAIRS) return;
    int e = g_topki[p];
    int pos = atomicAdd(&g_cursor[e], 1);
    g_perm[pos] = p;
}

// ---------------- 3xTF32 tensor-core GEMM ----------------------------------
// C[M,N] = A[M,K] * B  (B either NT: [N,K] row-major, or NN: [K,N] row-major)
// 3-pass error-compensated tf32: hi*hi + lo*hi + hi*lo, fp32 accumulate.
#define BM 128
#define BN 128
#define BK 16
#define LDK 20     // BK + 4 pad -> conflict-free fragment LDS

__device__ __forceinline__ uint32_t f2tf(float x) {
    uint32_t r; asm("cvt.rna.tf32.f32 %0, %1;" : "=r"(r) : "f"(x)); return r;
}

__device__ __forceinline__ void mma8(float* d, const uint32_t* a, uint32_t b0, uint32_t b1) {
    asm volatile("mma.sync.aligned.m16n8k8.row.col.f32.tf32.tf32.f32 "
        "{%0,%1,%2,%3}, {%4,%5,%6,%7}, {%8,%9}, {%0,%1,%2,%3};\n"
        : "+f"(d[0]), "+f"(d[1]), "+f"(d[2]), "+f"(d[3])
        : "r"(a[0]), "r"(a[1]), "r"(a[2]), "r"(a[3]), "r"(b0), "r"(b1));
}

// MODE 0: expert gate/up   A=x (gathered via perm), B=gup[e] (NT), out g_gu
// MODE 1: expert down      A=g_h (grouped rows),    B=dwn[e] (NT), out g_y (scaled+scatter)
// MODE 2: shared gate/up   A=x,  B=shg/shu (NN, ldb=FSH), out g_sraw
// MODE 3: shared down      A=g_s, B=shd (NN, ldb=DDIM),   out g_sh
template<int MODE, int K, int LDB>
__global__ __launch_bounds__(256) void gemm3x(const float* __restrict__ Aext,
                                              const float* __restrict__ Bw0,
                                              const float* __restrict__ Bw1)
{
    __shared__ uint32_t sAh[BM][LDK], sAl[BM][LDK];
    __shared__ uint32_t sBh[BN][LDK], sBl[BN][LDK];

    const int tid = threadIdx.x;
    const int m0 = blockIdx.y * BM;
    int cnt = 0, base = 0;
    const float* Bp = Bw0;
    int n0 = blockIdx.x * BN;   // B-tile offset (within its own matrix)
    int ocol = n0;              // output column base

    if (MODE == 0 || MODE == 1) {
        int e = blockIdx.z;
        cnt = g_count[e]; base = g_offset[e];
        if (m0 >= cnt) return;
        Bp = Bw0 + (MODE == 0 ? (size_t)e * 2 * FF * DDIM : (size_t)e * DDIM * FF);
    } else if (MODE == 2) {
        if (blockIdx.x >= 16) { Bp = Bw1; n0 = (blockIdx.x - 16) * BN; ocol = FSH + n0; }
    }

    const float* A = (MODE == 1) ? (const float*)g_h
                   : (MODE == 3) ? (const float*)g_s : Aext;

    // ---- loader addressing ----
    const int ar  = tid >> 2;          // A row within half-tile (0..63)
    const int ak4 = (tid & 3) * 4;     // A k offset
    const float* aptr[2];
#pragma unroll
    for (int i = 0; i < 2; i++) {
        int r = m0 + ar + i * 64;
        if (MODE == 0) {
            int rr = (r < cnt) ? r : (cnt - 1);
            int token = g_perm[base + rr] >> 1;
            aptr[i] = A + (size_t)token * K + ak4;
        } else if (MODE == 1) {
            int rr = (r < cnt) ? r : (cnt - 1);
            aptr[i] = A + (size_t)(base + rr) * K + ak4;
        } else {
            aptr[i] = A + (size_t)r * K + ak4;
        }
    }
    const float* bptr[2];
    int bn4[2] = {0, 0}, bk[2] = {0, 0};
#pragma unroll
    for (int i = 0; i < 2; i++) {
        int idx = tid + i * 256;
        if (MODE <= 1) {
            int n = idx >> 2; int k4 = (idx & 3) * 4;
            bptr[i] = Bp + (size_t)(n0 + n) * K + k4;
        } else {
            int k = idx >> 5; int n4 = (idx & 31) * 4;
            bk[i] = k; bn4[i] = n4;
            bptr[i] = Bp + (size_t)k * LDB + n0 + n4;
        }
    }

    const int wid = tid >> 5, lane = tid & 31;
    const int wm = wid >> 1, wn = wid & 1;
    const int lr = lane >> 2, lc = lane & 3;

    float acc[2][8][4];
#pragma unroll
    for (int a = 0; a < 2; a++)
#pragma unroll
        for (int b = 0; b < 8; b++)
#pragma unroll
            for (int c = 0; c < 4; c++) acc[a][b][c] = 0.f;

    float4 rA[2], rB[2];
#pragma unroll
    for (int i = 0; i < 2; i++) { rA[i] = *(const float4*)(aptr[i]); rB[i] = *(const float4*)(bptr[i]); }

    for (int k0 = 0; k0 < K; k0 += BK) {
        // ---- convert + store current chunk to smem ----
#pragma unroll
        for (int i = 0; i < 2; i++) {
            int row = ar + i * 64;
            float v[4] = {rA[i].x, rA[i].y, rA[i].z, rA[i].w};
            uint32_t h[4], l[4];
#pragma unroll
            for (int j = 0; j < 4; j++) { h[j] = f2tf(v[j]); l[j] = f2tf(v[j] - __uint_as_float(h[j])); }
            *(uint4*)&sAh[row][ak4] = make_uint4(h[0], h[1], h[2], h[3]);
            *(uint4*)&sAl[row][ak4] = make_uint4(l[0], l[1], l[2], l[3]);
        }
#pragma unroll
        for (int i = 0; i < 2; i++) {
            float v[4] = {rB[i].x, rB[i].y, rB[i].z, rB[i].w};
            uint32_t h[4], l[4];
#pragma unroll
            for (int j = 0; j < 4; j++) { h[j] = f2tf(v[j]); l[j] = f2tf(v[j] - __uint_as_float(h[j])); }
            if (MODE <= 1) {
                int idx = tid + i * 256; int n = idx >> 2; int k4 = (idx & 3) * 4;
                *(uint4*)&sBh[n][k4] = make_uint4(h[0], h[1], h[2], h[3]);
                *(uint4*)&sBl[n][k4] = make_uint4(l[0], l[1], l[2], l[3]);
            } else {
#pragma unroll
                for (int j = 0; j < 4; j++) { sBh[bn4[i] + j][bk[i]] = h[j]; sBl[bn4[i] + j][bk[i]] = l[j]; }
            }
        }
        __syncthreads();

        // ---- prefetch next chunk into registers ----
        if (k0 + BK < K) {
#pragma unroll
            for (int i = 0; i < 2; i++) {
                rA[i] = *(const float4*)(aptr[i] + (k0 + BK));
                if (MODE <= 1) rB[i] = *(const float4*)(bptr[i] + (k0 + BK));
                else           rB[i] = *(const float4*)(bptr[i] + (size_t)(k0 + BK) * LDB);
            }
        }

        // ---- compute: 2 k-steps x 3 passes x (2m x 8n) mma ----
#pragma unroll
        for (int ks = 0; ks < 2; ks++) {
            int k8 = ks * 8;
#pragma unroll
            for (int pass = 0; pass < 3; pass++) {
                const uint32_t (*sA)[LDK] = (pass == 1) ? sAl : sAh;
                const uint32_t (*sB)[LDK] = (pass == 2) ? sBl : sBh;
                uint32_t af[2][4];
#pragma unroll
                for (int mo = 0; mo < 2; mo++) {
                    int r = wm * 32 + mo * 16 + lr;
                    af[mo][0] = sA[r][k8 + lc];
                    af[mo][1] = sA[r + 8][k8 + lc];
                    af[mo][2] = sA[r][k8 + 4 + lc];
                    af[mo][3] = sA[r + 8][k8 + 4 + lc];
                }
#pragma unroll
                for (int nf = 0; nf < 8; nf++) {
                    int n = wn * 64 + nf * 8 + lr;
                    uint32_t b0 = sB[n][k8 + lc];
                    uint32_t b1 = sB[n][k8 + 4 + lc];
                    mma8(acc[0][nf], af[0], b0, b1);
                    mma8(acc[1][nf], af[1], b0, b1);
                }
            }
        }
        __syncthreads();
    }

    // ---- epilogue ----
#pragma unroll
    for (int mo = 0; mo < 2; mo++) {
#pragma unroll
        for (int rr = 0; rr < 2; rr++) {
            int r = m0 + wm * 32 + mo * 16 + rr * 8 + lr;
            float* dst = nullptr; float wscale = 1.f; bool ok = true;
            if (MODE == 0) {
                ok = r < cnt;
                if (ok) dst = g_gu + (size_t)(base + r) * 1024;
            } else if (MODE == 1) {
                ok = r < cnt;
                if (ok) { int pair = g_perm[base + r]; wscale = g_topkw[pair]; dst = g_y + (size_t)pair * DDIM; }
            } else if (MODE == 2) {
                dst = g_sraw + (size_t)r * (2 * FSH);
            } else {
                dst = g_sh + (size_t)r * DDIM;
            }
            if (!ok) continue;
#pragma unroll
            for (int nf = 0; nf < 8; nf++) {
                int c = ocol + wn * 64 + nf * 8 + lc * 2;
                float2 v;
                v.x = acc[mo][nf][rr * 2 + 0] * wscale;
                v.y = acc[mo][nf][rr * 2 + 1] * wscale;
                *(float2*)(dst + c) = v;
            }
        }
    }
}

// ---------------- activation passes ----------------------------------------
__global__ void k_act_expert() {
    int idx = blockIdx.x * 256 + threadIdx.x;      // PAIRS * (FF/4) = 524288
    if (idx >= PAIRS * (FF / 4)) return;
    int rr = idx >> 7;                 // FF/4 = 128
    int c  = (idx & 127) << 2;
    float4 g = *(const float4*)(g_gu + (size_t)rr * 1024 + c);
    float4 u = *(const float4*)(g_gu + (size_t)rr * 1024 + 512 + c);
    float4 h;
    h.x = g.x / (1.f + __expf(-g.x)) * u.x;
    h.y = g.y / (1.f + __expf(-g.y)) * u.y;
    h.z = g.z / (1.f + __expf(-g.z)) * u.z;
    h.w = g.w / (1.f + __expf(-g.w)) * u.w;
    *(float4*)(g_h + (size_t)rr * FF + c) = h;
}

__global__ void k_act_shared() {
    int idx = blockIdx.x * 256 + threadIdx.x;      // NTOK * (FSH/4) = 1048576
    if (idx >= NTOK * (FSH / 4)) return;
    int rr = idx >> 9;                 // FSH/4 = 512
    int c  = (idx & 511) << 2;
    float4 g = *(const float4*)(g_sraw + (size_t)rr * 4096 + c);
    float4 u = *(const float4*)(g_sraw + (size_t)rr * 4096 + 2048 + c);
    float4 h;
    h.x = g.x / (1.f + __expf(-g.x)) * u.x;
    h.y = g.y / (1.f + __expf(-g.y)) * u.y;
    h.z = g.z / (1.f + __expf(-g.z)) * u.z;
    h.w = g.w / (1.f + __expf(-g.w)) * u.w;
    *(float4*)(g_s + (size_t)rr * FSH + c) = h;
}

// out[t,d] = y0 + y1 + sgate * shared
__global__ void k_combine(float* __restrict__ out) {
    int i = blockIdx.x * blockDim.x + threadIdx.x;
    if (i >= NTOK * (DDIM / 4)) return;
    int t = i >> 8;
    int c = (i & 255) << 2;
    float4 y0 = *(const float4*)(g_y + (size_t)(2 * t + 0) * DDIM + c);
    float4 y1 = *(const float4*)(g_y + (size_t)(2 * t + 1) * DDIM + c);
    float4 sh = *(const float4*)(g_sh + (size_t)t * DDIM + c);
    float sg = g_sgate[t];
    float4 o;
    o.x = y0.x + y1.x + sg * sh.x;
    o.y = y0.y + y1.y + sg * sh.y;
    o.z = y0.z + y1.z + sg * sh.z;
    o.w = y0.w + y1.w + sg * sh.w;
    *(float4*)(out + (size_t)t * DDIM + c) = o;
}

// deterministic aux-loss reduction (fixed-order tree)
__global__ void k_aux(float* __restrict__ out, int out_size) {
    __shared__ float sred[256];
    float le[EXP];
#pragma unroll
    for (int e = 0; e < EXP; e++) le[e] = 0.f;
    for (int t = threadIdx.x; t < NTOK; t += 256)
#pragma unroll
        for (int e = 0; e < EXP; e++) le[e] += g_probs[(size_t)t * EXP + e];

    float aux = 0.f;
    for (int e = 0; e < EXP; e++) {
        sred[threadIdx.x] = le[e];
        __syncthreads();
        for (int s = 128; s; s >>= 1) {
            if (threadIdx.x < s) sred[threadIdx.x] += sred[threadIdx.x + s];
            __syncthreads();
        }
        if (threadIdx.x == 0) {
            float load = sred[0] * (1.f / NTOK);
            float d = load - (1.f / EXP);
            aux += d * d;
        }
        __syncthreads();
    }
    if (threadIdx.x == 0 && out_size > NTOK * DDIM)
        out[NTOK * DDIM] = 0.001f * aux;
}

// ---------------- launch -----------------------------------------------------
extern "C" void kernel_launch(void* const* d_in, const int* in_sizes, int n_in,
                              void* d_out, int out_size) {
    const float* x   = (const float*)d_in[0];   // [B,T,D]
    const float* gup = (const float*)d_in[1];   // [E,2F,D]
    const float* dwn = (const float*)d_in[2];   // [E,D,F]
    const float* rw  = (const float*)d_in[3];   // [D,E]
    const float* shg = (const float*)d_in[4];   // [D,FS]
    const float* shu = (const float*)d_in[5];   // [D,FS]
    const float* shd = (const float*)d_in[6];   // [FS,D]
    const float* sgw = (const float*)d_in[7];   // [D,1]
    float* out = (float*)d_out;

    k_zero<<<1, 32>>>();
    k_router<<<NTOK / 4, 128>>>(x, rw, sgw);
    k_scan<<<1, 1>>>();
    k_scatter<<<PAIRS / 256, 256>>>();

    // shared gate/up first (independent of routing) for better overlap tails
    gemm3x<2, 1024, FSH><<<dim3(32, 16, 1), 256>>>(x, shg, shu);
    gemm3x<0, 1024, 1><<<dim3(8, 16, EXP), 256>>>(x, gup, nullptr);
    k_act_expert<<<PAIRS * (FF / 4) / 256, 256>>>();
    gemm3x<1, 512, 1><<<dim3(8, 16, EXP), 256>>>(nullptr, dwn, nullptr);
    k_act_shared<<<NTOK * (FSH / 4) / 256, 256>>>();
    gemm3x<3, 2048, DDIM><<<dim3(8, 16, 1), 256>>>(nullptr, shd, nullptr);

    k_combine<<<(NTOK * (DDIM / 4) + 255) / 256, 256>>>(out);
    k_aux<<<1, 256>>>(out, out_size);
}

// round 4
// speedup vs baseline: 1.7542x; 1.7542x over previous
#include <cuda_runtime.h>
#include <cuda_fp16.h>
#include <cstdint>

// Problem constants
#define NTOK 2048          // B*T
#define DDIM 1024
#define EXP  16
#define FF   512
#define FSH  2048
#define PAIRS (NTOK*2)

// ---------------- scratch (device globals) ----------------------------------
__device__ float g_probs[NTOK * EXP];
__device__ float g_topkw[PAIRS];
__device__ int   g_topki[PAIRS];
__device__ float g_sgate[NTOK];
__device__ int   g_count[EXP];
__device__ int   g_offset[EXP];
__device__ int   g_cursor[EXP];
__device__ int   g_perm[PAIRS];
__device__ float g_gu  [(size_t)PAIRS * 1024];   // expert gate/up raw accum (f32)
__device__ float g_y   [(size_t)PAIRS * DDIM];   // weighted expert outputs
__device__ float g_sraw[(size_t)NTOK * 2 * FSH]; // shared gate/up raw accum
__device__ float g_shf [(size_t)NTOK * DDIM];    // shared output (f32)

// fp16 hi/lo packed as u32 (2 fp16 per u32), row-major [rows][K/2] u32
__device__ uint32_t g_xh  [NTOK * 512],        g_xl  [NTOK * 512];        // x      [T][D]
__device__ uint32_t g_wgh [EXP * 1024 * 512],  g_wgl [EXP * 1024 * 512];  // gup    [E*2F][D]
__device__ uint32_t g_wdh [EXP * 1024 * 256],  g_wdl [EXP * 1024 * 256];  // down   [E*D][F]
__device__ uint32_t g_g1h [FSH * 512],         g_g1l [FSH * 512];         // sh gate[FS][D]
__device__ uint32_t g_u1h [FSH * 512],         g_u1l [FSH * 512];         // sh up  [FS][D]
__device__ uint32_t g_d1h [DDIM * 1024],       g_d1l [DDIM * 1024];       // sh down[D][FS]
__device__ uint32_t g_ehh [PAIRS * 256],       g_ehl [PAIRS * 256];       // exp hid[P][F]
__device__ uint32_t g_shh [NTOK * 1024],       g_shl [NTOK * 1024];       // sh hid [T][FS]

// ---------------- asm helpers ------------------------------------------------
__device__ __forceinline__ uint32_t smem_u32(const void* p) {
    uint32_t a;
    asm("{ .reg .u64 t; cvta.to.shared.u64 t, %1; cvt.u32.u64 %0, t; }" : "=r"(a) : "l"(p));
    return a;
}
#define CPA(d, s) asm volatile("cp.async.cg.shared.global [%0], [%1], 16;" :: "r"(d), "l"(s) : "memory")
#define CPC()     asm volatile("cp.async.commit_group;" ::: "memory")
#define LDSM4(r, a) \
    asm volatile("ldmatrix.sync.aligned.m8n8.x4.shared.b16 {%0,%1,%2,%3}, [%4];" \
        : "=r"((r)[0]), "=r"((r)[1]), "=r"((r)[2]), "=r"((r)[3]) : "r"(a))
#define MMA16(d, a, b0, b1) \
    asm volatile("mma.sync.aligned.m16n8k16.row.col.f32.f16.f16.f32 " \
        "{%0,%1,%2,%3},{%4,%5,%6,%7},{%8,%9},{%0,%1,%2,%3};" \
        : "+f"((d)[0]), "+f"((d)[1]), "+f"((d)[2]), "+f"((d)[3]) \
        : "r"((a)[0]), "r"((a)[1]), "r"((a)[2]), "r"((a)[3]), "r"(b0), "r"(b1))

// ---------------- small kernels ---------------------------------------------
__global__ void k_zero() { int i = threadIdx.x; if (i < EXP) g_count[i] = 0; }

__global__ void k_router(const float* __restrict__ x, const float* __restrict__ rw,
                         const float* __restrict__ sgw) {
    int t = blockIdx.x * 4 + (threadIdx.x >> 5);
    int lane = threadIdx.x & 31;
    if (t >= NTOK) return;
    const float* xr = x + (size_t)t * DDIM;
    float acc[EXP];
#pragma unroll
    for (int e = 0; e < EXP; e++) acc[e] = 0.f;
    float sg = 0.f;
    for (int j = lane; j < DDIM; j += 32) {
        float xv = xr[j];
        const float* r = rw + (size_t)j * EXP;
#pragma unroll
        for (int e = 0; e < EXP; e++) acc[e] = fmaf(xv, r[e], acc[e]);
        sg = fmaf(xv, sgw[j], sg);
    }
#pragma unroll
    for (int off = 16; off; off >>= 1) {
#pragma unroll
        for (int e = 0; e < EXP; e++) acc[e] += __shfl_xor_sync(0xffffffffu, acc[e], off);
        sg += __shfl_xor_sync(0xffffffffu, sg, off);
    }
    float mx = acc[0];
#pragma unroll
    for (int e = 1; e < EXP; e++) mx = fmaxf(mx, acc[e]);
    float pr[EXP]; float sum = 0.f;
#pragma unroll
    for (int e = 0; e < EXP; e++) { pr[e] = __expf(acc[e] - mx); sum += pr[e]; }
    float inv = 1.f / sum;
#pragma unroll
    for (int e = 0; e < EXP; e++) pr[e] *= inv;
    if (lane < EXP) g_probs[(size_t)t * EXP + lane] = pr[lane];
    if (lane == 0) {
        int i1 = 0; float p1 = pr[0];
#pragma unroll
        for (int e = 1; e < EXP; e++) if (pr[e] > p1) { p1 = pr[e]; i1 = e; }
        int i2 = (i1 == 0) ? 1 : 0; float p2 = pr[i2];
#pragma unroll
        for (int e = 0; e < EXP; e++) if (e != i1 && pr[e] > p2) { p2 = pr[e]; i2 = e; }
        float s2 = p1 + p2; if (s2 < 1e-9f) s2 = 1e-9f;
        g_topkw[t * 2 + 0] = p1 / s2;  g_topkw[t * 2 + 1] = p2 / s2;
        g_topki[t * 2 + 0] = i1;       g_topki[t * 2 + 1] = i2;
        atomicAdd(&g_count[i1], 1);    atomicAdd(&g_count[i2], 1);
        g_sgate[t] = 1.f / (1.f + __expf(-sg));
    }
}

__global__ void k_scan() {
    int s = 0;
    for (int e = 0; e < EXP; e++) { g_offset[e] = s; g_cursor[e] = s; s += g_count[e]; }
}
__global__ void k_scatter() {
    int p = blockIdx.x * 256 + threadIdx.x;
    if (p >= PAIRS) return;
    int e = g_topki[p];
    int pos = atomicAdd(&g_cursor[e], 1);
    g_perm[pos] = p;
}

// ---------------- fp16 hi/lo split helpers ----------------------------------
__device__ __forceinline__ void split4h(float x0, float x1, float x2, float x3,
                                        uint32_t& h0, uint32_t& h1, uint32_t& l0, uint32_t& l1) {
    __half2 a = __floats2half2_rn(x0, x1);      // .x = x0 (low 16 bits)
    __half2 b = __floats2half2_rn(x2, x3);
    float2 af = __half22float2(a), bf = __half22float2(b);
    __half2 ra = __floats2half2_rn(x0 - af.x, x1 - af.y);
    __half2 rb = __floats2half2_rn(x2 - bf.x, x3 - bf.y);
    h0 = *reinterpret_cast<uint32_t*>(&a);
    h1 = *reinterpret_cast<uint32_t*>(&b);
    l0 = *reinterpret_cast<uint32_t*>(&ra);
    l1 = *reinterpret_cast<uint32_t*>(&rb);
}

__global__ void k_cvt(const float* __restrict__ in, uint32_t* __restrict__ oh,
                      uint32_t* __restrict__ ol, int n4) {
    int i = blockIdx.x * 256 + threadIdx.x;
    if (i >= n4) return;
    float4 v = ((const float4*)in)[i];
    uint32_t h0, h1, l0, l1;
    split4h(v.x, v.y, v.z, v.w, h0, h1, l0, l1);
    ((uint2*)oh)[i] = make_uint2(h0, h1);
    ((uint2*)ol)[i] = make_uint2(l0, l1);
}

// transpose-convert: in [Kdim][Ndim] f32 -> out [Ndim][Kdim/2] u32
__global__ void k_cvt_t(const float* __restrict__ in, uint32_t* __restrict__ oh,
                        uint32_t* __restrict__ ol, int Kdim, int Ndim) {
    __shared__ float tile[32][33];
    int k0 = blockIdx.y * 32, n0 = blockIdx.x * 32;
    int tx = threadIdx.x, ty = threadIdx.y;  // 32 x 8
#pragma unroll
    for (int i = 0; i < 4; i++)
        tile[ty + i * 8][tx] = in[(size_t)(k0 + ty + i * 8) * Ndim + n0 + tx];
    __syncthreads();
    int t = ty * 32 + tx;
    int nl = t >> 3, q = t & 7;
    size_t orow = (size_t)(n0 + nl) * (Kdim / 2) + (k0 >> 1);
#pragma unroll
    for (int j = 0; j < 2; j++) {
        int idx = q * 2 + j, kl = idx * 2;
        float x0 = tile[kl][nl], x1 = tile[kl + 1][nl];
        __half2 h = __floats2half2_rn(x0, x1);
        float2 hf = __half22float2(h);
        __half2 l = __floats2half2_rn(x0 - hf.x, x1 - hf.y);
        oh[orow + idx] = *reinterpret_cast<uint32_t*>(&h);
        ol[orow + idx] = *reinterpret_cast<uint32_t*>(&l);
    }
}

// ---------------- HMMA GEMM: 128x128 tile, BK=64, fp16 hi/lo 3-pass ---------
#define LDA    72           // halfs per smem row (64 + 8 pad; 144B, conflict-free ldmatrix)
#define ROWB   144
#define MATB   (128 * ROWB) // 18432 bytes per matrix per stage
#define STAGE  (4 * MATB)   // Ah, Al, Bh, Bl
#define SMBYTES (2 * STAGE)

// MODE 0: expert gate/up; 1: expert down; 2: shared gate/up; 3: shared down
template<int MODE, int KD>
__global__ void __launch_bounds__(256, 1) gemm_hmma() {
    constexpr int NC = KD / 64;
    constexpr int KU = KD / 2;         // u32 per gmem row
    extern __shared__ char sm[];
    const int tid = threadIdx.x;
    const int m0 = blockIdx.y * 128;
    const int bx = blockIdx.x;
    int n0 = bx * 128, ocol = n0;
    int cnt = 0, basep = 0;
    if (MODE <= 1) {
        int e = blockIdx.z;
        cnt = g_count[e]; basep = g_offset[e];
        if (m0 >= cnt) return;
    }

    // per-thread load row: r = tid>>1 (0..127), lc = tid&1 selects 64B half of the 128B row
    const int lr = tid >> 1, lc = tid & 1;
    const uint32_t *aH, *aL, *bH, *bL;
    if (MODE == 0) {
        int rr = m0 + lr; if (rr >= cnt) rr = cnt - 1;
        int token = g_perm[basep + rr] >> 1;
        aH = g_xh + (size_t)token * KU;  aL = g_xl + (size_t)token * KU;
        int e = blockIdx.z;
        bH = g_wgh + ((size_t)e * 1024 + n0 + lr) * KU;
        bL = g_wgl + ((size_t)e * 1024 + n0 + lr) * KU;
    } else if (MODE == 1) {
        int rr = m0 + lr; if (rr >= cnt) rr = cnt - 1;
        aH = g_ehh + (size_t)(basep + rr) * KU;  aL = g_ehl + (size_t)(basep + rr) * KU;
        int e = blockIdx.z;
        bH = g_wdh + ((size_t)e * 1024 + n0 + lr) * KU;
        bL = g_wdl + ((size_t)e * 1024 + n0 + lr) * KU;
    } else if (MODE == 2) {
        aH = g_xh + (size_t)(m0 + lr) * KU;  aL = g_xl + (size_t)(m0 + lr) * KU;
        if (bx < 16) {
            bH = g_g1h + (size_t)(n0 + lr) * KU;  bL = g_g1l + (size_t)(n0 + lr) * KU;
        } else {
            int nn = (bx - 16) * 128 + lr;
            bH = g_u1h + (size_t)nn * KU;  bL = g_u1l + (size_t)nn * KU;
            ocol = FSH + (bx - 16) * 128;
        }
    } else {
        aH = g_shh + (size_t)(m0 + lr) * KU;  aL = g_shl + (size_t)(m0 + lr) * KU;
        bH = g_d1h + (size_t)(n0 + lr) * KU;  bL = g_d1l + (size_t)(n0 + lr) * KU;
    }

    const uint32_t sb = smem_u32(sm);

    // chunk c -> stage s: each thread cp.asyncs 4x16B per matrix
    auto load = [&](int c, int s) {
        uint32_t dst = sb + s * STAGE + lr * ROWB + lc * 64;
        int gof = c * 32 + lc * 16;   // u32 offset into row
#pragma unroll
        for (int i = 0; i < 4; i++) {
            CPA(dst + 0 * MATB + i * 16, aH + gof + i * 4);
            CPA(dst + 1 * MATB + i * 16, aL + gof + i * 4);
            CPA(dst + 2 * MATB + i * 16, bH + gof + i * 4);
            CPA(dst + 3 * MATB + i * 16, bL + gof + i * 4);
        }
    };

    const int w = tid >> 5, lane = tid & 31;
    const int wr = (w >> 1) * 32, wc = (w & 1) * 64;

    float acc[2][8][4];
#pragma unroll
    for (int a = 0; a < 2; a++)
#pragma unroll
        for (int b = 0; b < 8; b++)
#pragma unroll
            for (int c = 0; c < 4; c++) acc[a][b][c] = 0.f;

    load(0, 0); CPC();
    load(1, 1); CPC();

    for (int c = 0; c < NC; c++) {
        if (c == NC - 1) asm volatile("cp.async.wait_group 0;" ::: "memory");
        else             asm volatile("cp.async.wait_group 1;" ::: "memory");
        __syncthreads();

        uint32_t stg = sb + (c & 1) * STAGE;
#pragma unroll
        for (int ks = 0; ks < 4; ks++) {
            int ko = ks * 32;  // byte offset (16 halfs)
            uint32_t ah[2][4], al[2][4];
#pragma unroll
            for (int mt = 0; mt < 2; mt++) {
                uint32_t ad = stg + (wr + mt * 16 + (lane & 15)) * ROWB + ko + (lane >> 4) * 16;
                LDSM4(ah[mt], ad);
                LDSM4(al[mt], ad + MATB);
            }
            uint32_t bh[4][4], bl[4][4];
#pragma unroll
            for (int p = 0; p < 4; p++) {
                uint32_t bd = stg + 2 * MATB + (wc + p * 16 + (lane & 15)) * ROWB + ko + (lane >> 4) * 16;
                LDSM4(bh[p], bd);
                LDSM4(bl[p], bd + MATB);
            }
#pragma unroll
            for (int mt = 0; mt < 2; mt++)
#pragma unroll
                for (int p = 0; p < 4; p++) {
                    MMA16(acc[mt][2 * p],     ah[mt], bh[p][0], bh[p][2]);
                    MMA16(acc[mt][2 * p + 1], ah[mt], bh[p][1], bh[p][3]);
                    MMA16(acc[mt][2 * p],     ah[mt], bl[p][0], bl[p][2]);
                    MMA16(acc[mt][2 * p + 1], ah[mt], bl[p][1], bl[p][3]);
                    MMA16(acc[mt][2 * p],     al[mt], bh[p][0], bh[p][2]);
                    MMA16(acc[mt][2 * p + 1], al[mt], bh[p][1], bh[p][3]);
                }
        }
        __syncthreads();
        if (c + 2 < NC) { load(c + 2, c & 1); CPC(); }
    }

    // epilogue
#pragma unroll
    for (int mt = 0; mt < 2; mt++) {
#pragma unroll
        for (int rh = 0; rh < 2; rh++) {
            int r = wr + mt * 16 + rh * 8 + (lane >> 2);   // row within tile
            int gr = m0 + r;
            float* dst = nullptr; float ws = 1.f; bool ok = true;
            if (MODE == 0) {
                ok = gr < cnt;
                if (ok) dst = g_gu + (size_t)(basep + gr) * 1024;
            } else if (MODE == 1) {
                ok = gr < cnt;
                if (ok) { int pair = g_perm[basep + gr]; ws = g_topkw[pair]; dst = g_y + (size_t)pair * DDIM; }
            } else if (MODE == 2) {
                dst = g_sraw + (size_t)gr * (2 * FSH);
            } else {
                dst = g_shf + (size_t)gr * DDIM;
            }
            if (!ok) continue;
#pragma unroll
            for (int nt = 0; nt < 8; nt++) {
                int col = ocol + wc + nt * 8 + (lane & 3) * 2;
                float2 v;
                v.x = acc[mt][nt][rh * 2 + 0] * ws;
                v.y = acc[mt][nt][rh * 2 + 1] * ws;
                *(float2*)(dst + col) = v;
            }
        }
    }
}

// ---------------- activations (write packed fp16 hi/lo) ----------------------
__global__ void k_act_expert() {
    int i = blockIdx.x * 256 + threadIdx.x;          // PAIRS * FF/4
    if (i >= PAIRS * (FF / 4)) return;
    int rr = i >> 7;  int c4 = (i & 127) << 2;
    const float* row = g_gu + (size_t)rr * 1024;
    float4 g = *(const float4*)(row + c4);
    float4 u = *(const float4*)(row + 512 + c4);
    float h0 = g.x / (1.f + __expf(-g.x)) * u.x;
    float h1 = g.y / (1.f + __expf(-g.y)) * u.y;
    float h2 = g.z / (1.f + __expf(-g.z)) * u.z;
    float h3 = g.w / (1.f + __expf(-g.w)) * u.w;
    uint32_t hh0, hh1, ll0, ll1;
    split4h(h0, h1, h2, h3, hh0, hh1, ll0, ll1);
    size_t o = (size_t)rr * 256 + (c4 >> 1);
    *(uint2*)(g_ehh + o) = make_uint2(hh0, hh1);
    *(uint2*)(g_ehl + o) = make_uint2(ll0, ll1);
}

__global__ void k_act_shared() {
    int i = blockIdx.x * 256 + threadIdx.x;          // NTOK * FSH/4
    if (i >= NTOK * (FSH / 4)) return;
    int rr = i >> 9;  int c4 = (i & 511) << 2;
    const float* row = g_sraw + (size_t)rr * 4096;
    float4 g = *(const float4*)(row + c4);
    float4 u = *(const float4*)(row + 2048 + c4);
    float h0 = g.x / (1.f + __expf(-g.x)) * u.x;
    float h1 = g.y / (1.f + __expf(-g.y)) * u.y;
    float h2 = g.z / (1.f + __expf(-g.z)) * u.z;
    float h3 = g.w / (1.f + __expf(-g.w)) * u.w;
    uint32_t hh0, hh1, ll0, ll1;
    split4h(h0, h1, h2, h3, hh0, hh1, ll0, ll1);
    size_t o = (size_t)rr * 1024 + (c4 >> 1);
    *(uint2*)(g_shh + o) = make_uint2(hh0, hh1);
    *(uint2*)(g_shl + o) = make_uint2(ll0, ll1);
}

// out[t,d] = y0 + y1 + sgate * shared
__global__ void k_combine(float* __restrict__ out) {
    int i = blockIdx.x * blockDim.x + threadIdx.x;
    if (i >= NTOK * (DDIM / 4)) return;
    int t = i >> 8;
    int c = (i & 255) << 2;
    float4 y0 = *(const float4*)(g_y + (size_t)(2 * t + 0) * DDIM + c);
    float4 y1 = *(const float4*)(g_y + (size_t)(2 * t + 1) * DDIM + c);
    float4 sh = *(const float4*)(g_shf + (size_t)t * DDIM + c);
    float sg = g_sgate[t];
    float4 o;
    o.x = y0.x + y1.x + sg * sh.x;
    o.y = y0.y + y1.y + sg * sh.y;
    o.z = y0.z + y1.z + sg * sh.z;
    o.w = y0.w + y1.w + sg * sh.w;
    *(float4*)(out + (size_t)t * DDIM + c) = o;
}

__global__ void k_aux(float* __restrict__ out, int out_size) {
    __shared__ float sred[256];
    float le[EXP];
#pragma unroll
    for (int e = 0; e < EXP; e++) le[e] = 0.f;
    for (int t = threadIdx.x; t < NTOK; t += 256)
#pragma unroll
        for (int e = 0; e < EXP; e++) le[e] += g_probs[(size_t)t * EXP + e];
    float aux = 0.f;
    for (int e = 0; e < EXP; e++) {
        sred[threadIdx.x] = le[e];
        __syncthreads();
        for (int s = 128; s; s >>= 1) {
            if (threadIdx.x < s) sred[threadIdx.x] += sred[threadIdx.x + s];
            __syncthreads();
        }
        if (threadIdx.x == 0) {
            float load = sred[0] * (1.f / NTOK);
            float d = load - (1.f / EXP);
            aux += d * d;
        }
        __syncthreads();
    }
    if (threadIdx.x == 0 && out_size > NTOK * DDIM)
        out[NTOK * DDIM] = 0.001f * aux;
}

// ---------------- launch -----------------------------------------------------
extern "C" void kernel_launch(void* const* d_in, const int* in_sizes, int n_in,
                              void* d_out, int out_size) {
    const float* x   = (const float*)d_in[0];   // [B,T,D]
    const float* gup = (const float*)d_in[1];   // [E,2F,D]
    const float* dwn = (const float*)d_in[2];   // [E,D,F]
    const float* rw  = (const float*)d_in[3];   // [D,E]
    const float* shg = (const float*)d_in[4];   // [D,FS]
    const float* shu = (const float*)d_in[5];   // [D,FS]
    const float* shd = (const float*)d_in[6];   // [FS,D]
    const float* sgw = (const float*)d_in[7];   // [D,1]
    float* out = (float*)d_out;

    cudaFuncSetAttribute((const void*)gemm_hmma<0, 1024>, cudaFuncAttributeMaxDynamicSharedMemorySize, SMBYTES);
    cudaFuncSetAttribute((const void*)gemm_hmma<1, 512>,  cudaFuncAttributeMaxDynamicSharedMemorySize, SMBYTES);
    cudaFuncSetAttribute((const void*)gemm_hmma<2, 1024>, cudaFuncAttributeMaxDynamicSharedMemorySize, SMBYTES);
    cudaFuncSetAttribute((const void*)gemm_hmma<3, 2048>, cudaFuncAttributeMaxDynamicSharedMemorySize, SMBYTES);

    uint32_t *xh, *xl, *wgh, *wgl, *wdh, *wdl, *g1h, *g1l, *u1h, *u1l, *d1h, *d1l;
    cudaGetSymbolAddress((void**)&xh,  g_xh);  cudaGetSymbolAddress((void**)&xl,  g_xl);
    cudaGetSymbolAddress((void**)&wgh, g_wgh); cudaGetSymbolAddress((void**)&wgl, g_wgl);
    cudaGetSymbolAddress((void**)&wdh, g_wdh); cudaGetSymbolAddress((void**)&wdl, g_wdl);
    cudaGetSymbolAddress((void**)&g1h, g_g1h); cudaGetSymbolAddress((void**)&g1l, g_g1l);
    cudaGetSymbolAddress((void**)&u1h, g_u1h); cudaGetSymbolAddress((void**)&u1l, g_u1l);
    cudaGetSymbolAddress((void**)&d1h, g_d1h); cudaGetSymbolAddress((void**)&d1l, g_d1l);

    k_zero<<<1, 32>>>();
    k_router<<<NTOK / 4, 128>>>(x, rw, sgw);
    k_scan<<<1, 1>>>();
    k_scatter<<<PAIRS / 256, 256>>>();

    // operand conversions
    k_cvt<<<(NTOK * DDIM / 4) / 256, 256>>>(x, xh, xl, NTOK * DDIM / 4);
    k_cvt<<<(EXP * 1024 * 1024 / 4) / 256, 256>>>(gup, wgh, wgl, EXP * 1024 * 1024 / 4);
    k_cvt<<<(EXP * 1024 * 512 / 4) / 256, 256>>>(dwn, wdh, wdl, EXP * 1024 * 512 / 4);
    k_cvt_t<<<dim3(FSH / 32, DDIM / 32), dim3(32, 8)>>>(shg, g1h, g1l, DDIM, FSH);
    k_cvt_t<<<dim3(FSH / 32, DDIM / 32), dim3(32, 8)>>>(shu, u1h, u1l, DDIM, FSH);
    k_cvt_t<<<dim3(DDIM / 32, FSH / 32), dim3(32, 8)>>>(shd, d1h, d1l, FSH, DDIM);

    // GEMMs
    gemm_hmma<2, 1024><<<dim3(32, 16), 256, SMBYTES>>>();            // shared gate/up
    gemm_hmma<0, 1024><<<dim3(8, 32, EXP), 256, SMBYTES>>>();        // expert gate/up
    k_act_expert<<<PAIRS * (FF / 4) / 256, 256>>>();
    k_act_shared<<<NTOK * (FSH / 4) / 256, 256>>>();
    gemm_hmma<1, 512><<<dim3(8, 32, EXP), 256, SMBYTES>>>();         // expert down
    gemm_hmma<3, 2048><<<dim3(8, 16), 256, SMBYTES>>>();             // shared down

    k_combine<<<(NTOK * (DDIM / 4) + 255) / 256, 256>>>(out);
    k_aux<<<1, 256>>>(out, out_size);
}

// round 5
// speedup vs baseline: 1.9811x; 1.1294x over previous
#include <cuda_runtime.h>
#include <cuda_fp16.h>
#include <cstdint>

// Problem constants
#define NTOK 2048          // B*T
#define DDIM 1024
#define EXP  16
#define FF   512
#define FSH  2048
#define PAIRS (NTOK*2)

// ---------------- scratch (device globals) ----------------------------------
__device__ float g_probs[NTOK * EXP];
__device__ float g_topkw[PAIRS];
__device__ int   g_topki[PAIRS];
__device__ float g_sgate[NTOK];
__device__ int   g_count[EXP];
__device__ int   g_offset[EXP];
__device__ int   g_cursor[EXP];
__device__ int   g_perm[PAIRS];
__device__ float g_y   [(size_t)PAIRS * DDIM];   // weighted expert outputs
__device__ float g_shf [(size_t)NTOK * DDIM];    // shared output (f32)

// fp16 hi/lo packed as u32 (2 fp16 per u32), row-major [rows][K/2] u32
__device__ uint32_t g_xh  [NTOK * 512],        g_xl  [NTOK * 512];        // x      [T][D]
__device__ uint32_t g_wgh [EXP * 1024 * 512],  g_wgl [EXP * 1024 * 512];  // gup    [E*2F][D]
__device__ uint32_t g_wdh [EXP * 1024 * 256],  g_wdl [EXP * 1024 * 256];  // down   [E*D][F]
__device__ uint32_t g_g1h [FSH * 512],         g_g1l [FSH * 512];         // sh gate[FS][D]
__device__ uint32_t g_u1h [FSH * 512],         g_u1l [FSH * 512];         // sh up  [FS][D]
__device__ uint32_t g_d1h [DDIM * 1024],       g_d1l [DDIM * 1024];       // sh down[D][FS]
__device__ uint32_t g_ehh [PAIRS * 256],       g_ehl [PAIRS * 256];       // exp hid[P][F]
__device__ uint32_t g_shh [NTOK * 1024],       g_shl [NTOK * 1024];       // sh hid [T][FS]

// ---------------- asm helpers ------------------------------------------------
__device__ __forceinline__ uint32_t smem_u32(const void* p) {
    uint32_t a;
    asm("{ .reg .u64 t; cvta.to.shared.u64 t, %1; cvt.u32.u64 %0, t; }" : "=r"(a) : "l"(p));
    return a;
}
#define CPA(d, s) asm volatile("cp.async.cg.shared.global [%0], [%1], 16;" :: "r"(d), "l"(s) : "memory")
#define CPC()     asm volatile("cp.async.commit_group;" ::: "memory")
#define CPW1()    asm volatile("cp.async.wait_group 1;" ::: "memory")
#define CPW0()    asm volatile("cp.async.wait_group 0;" ::: "memory")
#define LDSM4(r, a) \
    asm volatile("ldmatrix.sync.aligned.m8n8.x4.shared.b16 {%0,%1,%2,%3}, [%4];" \
        : "=r"((r)[0]), "=r"((r)[1]), "=r"((r)[2]), "=r"((r)[3]) : "r"(a))
#define MMA16(d, a, b0, b1) \
    asm volatile("mma.sync.aligned.m16n8k16.row.col.f32.f16.f16.f32 " \
        "{%0,%1,%2,%3},{%4,%5,%6,%7},{%8,%9},{%0,%1,%2,%3};" \
        : "+f"((d)[0]), "+f"((d)[1]), "+f"((d)[2]), "+f"((d)[3]) \
        : "r"((a)[0]), "r"((a)[1]), "r"((a)[2]), "r"((a)[3]), "r"(b0), "r"(b1))

// ---------------- small kernels ---------------------------------------------
__global__ void k_zero() { int i = threadIdx.x; if (i < EXP) g_count[i] = 0; }

__global__ void k_router(const float* __restrict__ x, const float* __restrict__ rw,
                         const float* __restrict__ sgw) {
    int t = blockIdx.x * 4 + (threadIdx.x >> 5);
    int lane = threadIdx.x & 31;
    if (t >= NTOK) return;
    const float* xr = x + (size_t)t * DDIM;
    float acc[EXP];
#pragma unroll
    for (int e = 0; e < EXP; e++) acc[e] = 0.f;
    float sg = 0.f;
    for (int j = lane; j < DDIM; j += 32) {
        float xv = xr[j];
        const float* r = rw + (size_t)j * EXP;
#pragma unroll
        for (int e = 0; e < EXP; e++) acc[e] = fmaf(xv, r[e], acc[e]);
        sg = fmaf(xv, sgw[j], sg);
    }
#pragma unroll
    for (int off = 16; off; off >>= 1) {
#pragma unroll
        for (int e = 0; e < EXP; e++) acc[e] += __shfl_xor_sync(0xffffffffu, acc[e], off);
        sg += __shfl_xor_sync(0xffffffffu, sg, off);
    }
    float mx = acc[0];
#pragma unroll
    for (int e = 1; e < EXP; e++) mx = fmaxf(mx, acc[e]);
    float pr[EXP]; float sum = 0.f;
#pragma unroll
    for (int e = 0; e < EXP; e++) { pr[e] = __expf(acc[e] - mx); sum += pr[e]; }
    float inv = 1.f / sum;
#pragma unroll
    for (int e = 0; e < EXP; e++) pr[e] *= inv;
    if (lane < EXP) g_probs[(size_t)t * EXP + lane] = pr[lane];
    if (lane == 0) {
        int i1 = 0; float p1 = pr[0];
#pragma unroll
        for (int e = 1; e < EXP; e++) if (pr[e] > p1) { p1 = pr[e]; i1 = e; }
        int i2 = (i1 == 0) ? 1 : 0; float p2 = pr[i2];
#pragma unroll
        for (int e = 0; e < EXP; e++) if (e != i1 && pr[e] > p2) { p2 = pr[e]; i2 = e; }
        float s2 = p1 + p2; if (s2 < 1e-9f) s2 = 1e-9f;
        g_topkw[t * 2 + 0] = p1 / s2;  g_topkw[t * 2 + 1] = p2 / s2;
        g_topki[t * 2 + 0] = i1;       g_topki[t * 2 + 1] = i2;
        atomicAdd(&g_count[i1], 1);    atomicAdd(&g_count[i2], 1);
        g_sgate[t] = 1.f / (1.f + __expf(-sg));
    }
}

__global__ void k_scan() {
    int s = 0;
    for (int e = 0; e < EXP; e++) { g_offset[e] = s; g_cursor[e] = s; s += g_count[e]; }
}
__global__ void k_scatter() {
    int p = blockIdx.x * 256 + threadIdx.x;
    if (p >= PAIRS) return;
    int e = g_topki[p];
    int pos = atomicAdd(&g_cursor[e], 1);
    g_perm[pos] = p;
}

// ---------------- fp16 hi/lo split helpers ----------------------------------
__device__ __forceinline__ void split2h(float x0, float x1, uint32_t& h, uint32_t& l) {
    __half2 a = __floats2half2_rn(x0, x1);
    float2 af = __half22float2(a);
    __half2 r = __floats2half2_rn(x0 - af.x, x1 - af.y);
    h = *reinterpret_cast<uint32_t*>(&a);
    l = *reinterpret_cast<uint32_t*>(&r);
}
__device__ __forceinline__ void split4h(float x0, float x1, float x2, float x3,
                                        uint32_t& h0, uint32_t& h1, uint32_t& l0, uint32_t& l1) {
    split2h(x0, x1, h0, l0);
    split2h(x2, x3, h1, l1);
}

// merged straight convert: x (N1), gup (N2), dwn (N3) in one launch
#define CVT_N1 (NTOK * DDIM / 4)
#define CVT_N2 (EXP * 1024 * 1024 / 4)
#define CVT_N3 (EXP * 1024 * 512 / 4)
__global__ void k_cvt_all(const float* __restrict__ x, const float* __restrict__ gup,
                          const float* __restrict__ dwn) {
    int i = blockIdx.x * 256 + threadIdx.x;
    const float* in; uint32_t *oh, *ol; int idx;
    if (i < CVT_N1)                { in = x;   oh = g_xh;  ol = g_xl;  idx = i; }
    else if (i < CVT_N1 + CVT_N2)  { in = gup; oh = g_wgh; ol = g_wgl; idx = i - CVT_N1; }
    else                           { in = dwn; oh = g_wdh; ol = g_wdl; idx = i - CVT_N1 - CVT_N2; }
    float4 v = ((const float4*)in)[idx];
    uint32_t h0, h1, l0, l1;
    split4h(v.x, v.y, v.z, v.w, h0, h1, l0, l1);
    ((uint2*)oh)[idx] = make_uint2(h0, h1);
    ((uint2*)ol)[idx] = make_uint2(l0, l1);
}

// z-batched transpose-convert: in [Kdim][Ndim] f32 -> out [Ndim][Kdim/2] u32
__global__ void k_cvt_t3(const float* __restrict__ shg, const float* __restrict__ shu,
                         const float* __restrict__ shd) {
    const float* in; uint32_t *oh, *ol; int Kdim, Ndim;
    if (blockIdx.z == 0)      { in = shg; oh = g_g1h; ol = g_g1l; Kdim = DDIM; Ndim = FSH; }
    else if (blockIdx.z == 1) { in = shu; oh = g_u1h; ol = g_u1l; Kdim = DDIM; Ndim = FSH; }
    else                      { in = shd; oh = g_d1h; ol = g_d1l; Kdim = FSH; Ndim = DDIM; }
    int k0 = blockIdx.y * 32, n0 = blockIdx.x * 32;
    if (k0 >= Kdim || n0 >= Ndim) return;
    __shared__ float tile[32][33];
    int tx = threadIdx.x, ty = threadIdx.y;  // 32 x 8
#pragma unroll
    for (int i = 0; i < 4; i++)
        tile[ty + i * 8][tx] = in[(size_t)(k0 + ty + i * 8) * Ndim + n0 + tx];
    __syncthreads();
    int t = ty * 32 + tx;
    int nl = t >> 3, q = t & 7;
    size_t orow = (size_t)(n0 + nl) * (Kdim / 2) + (k0 >> 1);
#pragma unroll
    for (int j = 0; j < 2; j++) {
        int idx = q * 2 + j, kl = idx * 2;
        uint32_t h, l;
        split2h(tile[kl][nl], tile[kl + 1][nl], h, l);
        oh[orow + idx] = h;
        ol[orow + idx] = l;
    }
}

// ---------------- HMMA GEMM core: 128x128 tile, BK=64, 3-pass, 3-stage ------
#define ROWB   144          // bytes per smem row (64 halfs + 8 pad)
#define MATB   (128 * ROWB) // 18432
#define STAGE  (4 * MATB)   // Ah, Al, Bh, Bl = 73728
#define SMBYTES (3 * STAGE) // 221184

// loads chunk c into stage s
__device__ __forceinline__ void g_load(uint32_t sb, int s, int c, int lr, int lc,
                                       const uint32_t* aH, const uint32_t* aL,
                                       const uint32_t* bH, const uint32_t* bL) {
    uint32_t dst = sb + s * STAGE + lr * ROWB + lc * 64;
    int gof = c * 32 + lc * 16;
#pragma unroll
    for (int i = 0; i < 4; i++) {
        CPA(dst + 0 * MATB + i * 16, aH + gof + i * 4);
        CPA(dst + 1 * MATB + i * 16, aL + gof + i * 4);
        CPA(dst + 2 * MATB + i * 16, bH + gof + i * 4);
        CPA(dst + 3 * MATB + i * 16, bL + gof + i * 4);
    }
}

// mainloop: 3-stage pipeline, produces acc[2][8][4] per thread
__device__ __forceinline__ void g_mainloop(float acc[2][8][4], uint32_t sb, int NC,
                                           int lr, int lc, int wr, int wc, int lane,
                                           const uint32_t* aH, const uint32_t* aL,
                                           const uint32_t* bH, const uint32_t* bL) {
    g_load(sb, 0, 0, lr, lc, aH, aL, bH, bL); CPC();
    g_load(sb, 1, 1, lr, lc, aH, aL, bH, bL); CPC();
    int s2 = 2;
    for (int c = 0; c < NC; c++) {
        if (c + 1 < NC) CPW1(); else CPW0();
        __syncthreads();
        if (c + 2 < NC) {
            g_load(sb, s2, c + 2, lr, lc, aH, aL, bH, bL); CPC();
            if (++s2 == 3) s2 = 0;
        }
        uint32_t stg = sb + (c % 3) * STAGE;
#pragma unroll
        for (int ks = 0; ks < 4; ks++) {
            int ko = ks * 32;
            uint32_t ah[2][4], al[2][4];
#pragma unroll
            for (int mt = 0; mt < 2; mt++) {
                uint32_t ad = stg + (wr + mt * 16 + (lane & 15)) * ROWB + ko + (lane >> 4) * 16;
                LDSM4(ah[mt], ad);
                LDSM4(al[mt], ad + MATB);
            }
            uint32_t bh[4][4], bl[4][4];
#pragma unroll
            for (int p = 0; p < 4; p++) {
                uint32_t bd = stg + 2 * MATB + (wc + p * 16 + (lane & 15)) * ROWB + ko + (lane >> 4) * 16;
                LDSM4(bh[p], bd);
                LDSM4(bl[p], bd + MATB);
            }
#pragma unroll
            for (int mt = 0; mt < 2; mt++)
#pragma unroll
                for (int p = 0; p < 4; p++) {
                    MMA16(acc[mt][2 * p],     ah[mt], bh[p][0], bh[p][2]);
                    MMA16(acc[mt][2 * p + 1], ah[mt], bh[p][1], bh[p][3]);
                    MMA16(acc[mt][2 * p],     ah[mt], bl[p][0], bl[p][2]);
                    MMA16(acc[mt][2 * p + 1], ah[mt], bl[p][1], bl[p][3]);
                    MMA16(acc[mt][2 * p],     al[mt], bh[p][0], bh[p][2]);
                    MMA16(acc[mt][2 * p + 1], al[mt], bh[p][1], bh[p][3]);
                }
        }
    }
    __syncthreads();   // smem may be reused by epilogue
}

// ---- up GEMM: x @ {gate,up}^T with fused silu*up -> packed fp16 hidden -----
// grid: [0,512) shared tiles (16 m x 32 f), [512, 4608) expert tiles (e, 32 m, 8 f)
__global__ void __launch_bounds__(256, 1) k_up() {
    extern __shared__ char sm[];
    const int tid = threadIdx.x;
    const int lr = tid >> 1, lc = tid & 1;
    const int w = tid >> 5, lane = tid & 31;
    const int wr = (w >> 1) * 32, wc = (w & 1) * 64;

    int bx = blockIdx.x;
    bool shmode; int e = 0, m0, f0, cnt = 0, basep = 0;
    if (bx < 512) {
        shmode = true;
        m0 = (bx >> 5) * 128; f0 = (bx & 31) * 64;
    } else {
        shmode = false;
        bx -= 512;
        e = bx >> 8; int rem = bx & 255;
        m0 = (rem >> 3) * 128; f0 = (rem & 7) * 64;
        cnt = g_count[e]; basep = g_offset[e];
        if (m0 >= cnt) return;
    }

    const uint32_t *aH, *aL, *bH, *bL;
    if (shmode) {
        aH = g_xh + (size_t)(m0 + lr) * 512;  aL = g_xl + (size_t)(m0 + lr) * 512;
        if (lr < 64) { bH = g_g1h + (size_t)(f0 + lr) * 512;       bL = g_g1l + (size_t)(f0 + lr) * 512; }
        else         { bH = g_u1h + (size_t)(f0 + lr - 64) * 512;  bL = g_u1l + (size_t)(f0 + lr - 64) * 512; }
    } else {
        int rr = m0 + lr; if (rr >= cnt) rr = cnt - 1;
        int token = g_perm[basep + rr] >> 1;
        aH = g_xh + (size_t)token * 512;  aL = g_xl + (size_t)token * 512;
        int brow = (lr < 64) ? (e * 1024 + f0 + lr) : (e * 1024 + 512 + f0 + lr - 64);
        bH = g_wgh + (size_t)brow * 512;  bL = g_wgl + (size_t)brow * 512;
    }

    const uint32_t sb = smem_u32(sm);
    float acc[2][8][4];
#pragma unroll
    for (int a = 0; a < 2; a++)
#pragma unroll
        for (int b = 0; b < 8; b++)
#pragma unroll
            for (int c = 0; c < 4; c++) acc[a][b][c] = 0.f;

    g_mainloop(acc, sb, 16, lr, lc, wr, wc, lane, aH, aL, bH, bL);

    // ---- fused epilogue: even warps hold gate cols 0..63, odd hold up 64..127
    float* xbuf = (float*)sm;            // [4][32][64] f32
    int p = w >> 1;
    if (w & 1) {
#pragma unroll
        for (int mt = 0; mt < 2; mt++)
#pragma unroll
            for (int nt = 0; nt < 8; nt++)
#pragma unroll
                for (int i = 0; i < 4; i++) {
                    int rl = mt * 16 + (i >> 1) * 8 + (lane >> 2);
                    int cl = nt * 8 + (lane & 3) * 2 + (i & 1);
                    xbuf[p * 2048 + rl * 64 + cl] = acc[mt][nt][i];
                }
    }
    __syncthreads();
    if (!(w & 1)) {
#pragma unroll
        for (int mt = 0; mt < 2; mt++)
#pragma unroll
            for (int rh = 0; rh < 2; rh++) {
                int rl = mt * 16 + rh * 8 + (lane >> 2);
                int gr = m0 + wr + rl;
                uint32_t *dh, *dl; bool ok = true;
                if (shmode) {
                    dh = g_shh + (size_t)gr * 1024 + (f0 >> 1);
                    dl = g_shl + (size_t)gr * 1024 + (f0 >> 1);
                } else {
                    ok = gr < cnt;
                    int row = ok ? (basep + gr) : 0;
                    dh = g_ehh + (size_t)row * 256 + (f0 >> 1);
                    dl = g_ehl + (size_t)row * 256 + (f0 >> 1);
                }
                if (!ok) continue;
#pragma unroll
                for (int nt = 0; nt < 8; nt++) {
                    int cc = nt * 8 + (lane & 3) * 2;
                    float gg0 = acc[mt][nt][rh * 2 + 0];
                    float gg1 = acc[mt][nt][rh * 2 + 1];
                    float u0 = xbuf[p * 2048 + rl * 64 + cc];
                    float u1 = xbuf[p * 2048 + rl * 64 + cc + 1];
                    float h0 = gg0 / (1.f + __expf(-gg0)) * u0;
                    float h1 = gg1 / (1.f + __expf(-gg1)) * u1;
                    uint32_t hh, ll;
                    split2h(h0, h1, hh, ll);
                    dh[cc >> 1] = hh;
                    dl[cc >> 1] = ll;
                }
            }
    }
}

// ---- down GEMM: hidden @ down^T ------------------------------------------
// grid: [0,128) shared tiles (16 m x 8 d), [128, 4224) expert tiles (e, 32 m, 8 d)
__global__ void __launch_bounds__(256, 1) k_down() {
    extern __shared__ char sm[];
    const int tid = threadIdx.x;
    const int lr = tid >> 1, lc = tid & 1;
    const int w = tid >> 5, lane = tid & 31;
    const int wr = (w >> 1) * 32, wc = (w & 1) * 64;

    int bx = blockIdx.x;
    bool shmode; int e = 0, m0, n0, cnt = 0, basep = 0, NC;
    if (bx < 128) {
        shmode = true;
        m0 = (bx >> 3) * 128; n0 = (bx & 7) * 128; NC = 32;
    } else {
        shmode = false;
        bx -= 128;
        e = bx >> 8; int rem = bx & 255;
        m0 = (rem >> 3) * 128; n0 = (rem & 7) * 128; NC = 8;
        cnt = g_count[e]; basep = g_offset[e];
        if (m0 >= cnt) return;
    }

    const uint32_t *aH, *aL, *bH, *bL;
    if (shmode) {
        aH = g_shh + (size_t)(m0 + lr) * 1024;  aL = g_shl + (size_t)(m0 + lr) * 1024;
        bH = g_d1h + (size_t)(n0 + lr) * 1024;  bL = g_d1l + (size_t)(n0 + lr) * 1024;
    } else {
        int rr = m0 + lr; if (rr >= cnt) rr = cnt - 1;
        aH = g_ehh + (size_t)(basep + rr) * 256;  aL = g_ehl + (size_t)(basep + rr) * 256;
        bH = g_wdh + (size_t)(e * 1024 + n0 + lr) * 256;
        bL = g_wdl + (size_t)(e * 1024 + n0 + lr) * 256;
    }

    const uint32_t sb = smem_u32(sm);
    float acc[2][8][4];
#pragma unroll
    for (int a = 0; a < 2; a++)
#pragma unroll
        for (int b = 0; b < 8; b++)
#pragma unroll
            for (int c = 0; c < 4; c++) acc[a][b][c] = 0.f;

    g_mainloop(acc, sb, NC, lr, lc, wr, wc, lane, aH, aL, bH, bL);

    // epilogue
#pragma unroll
    for (int mt = 0; mt < 2; mt++) {
#pragma unroll
        for (int rh = 0; rh < 2; rh++) {
            int r = wr + mt * 16 + rh * 8 + (lane >> 2);
            int gr = m0 + r;
            float* dst = nullptr; float ws = 1.f; bool ok = true;
            if (shmode) {
                dst = g_shf + (size_t)gr * DDIM;
            } else {
                ok = gr < cnt;
                if (ok) { int pair = g_perm[basep + gr]; ws = g_topkw[pair]; dst = g_y + (size_t)pair * DDIM; }
            }
            if (!ok) continue;
#pragma unroll
            for (int nt = 0; nt < 8; nt++) {
                int col = n0 + wc + nt * 8 + (lane & 3) * 2;
                float2 v;
                v.x = acc[mt][nt][rh * 2 + 0] * ws;
                v.y = acc[mt][nt][rh * 2 + 1] * ws;
                *(float2*)(dst + col) = v;
            }
        }
    }
}

// out[t,d] = y0 + y1 + sgate * shared
__global__ void k_combine(float* __restrict__ out) {
    int i = blockIdx.x * blockDim.x + threadIdx.x;
    if (i >= NTOK * (DDIM / 4)) return;
    int t = i >> 8;
    int c = (i & 255) << 2;
    float4 y0 = *(const float4*)(g_y + (size_t)(2 * t + 0) * DDIM + c);
    float4 y1 = *(const float4*)(g_y + (size_t)(2 * t + 1) * DDIM + c);
    float4 sh = *(const float4*)(g_shf + (size_t)t * DDIM + c);
    float sg = g_sgate[t];
    float4 o;
    o.x = y0.x + y1.x + sg * sh.x;
    o.y = y0.y + y1.y + sg * sh.y;
    o.z = y0.z + y1.z + sg * sh.z;
    o.w = y0.w + y1.w + sg * sh.w;
    *(float4*)(out + (size_t)t * DDIM + c) = o;
}

__global__ void k_aux(float* __restrict__ out, int out_size) {
    __shared__ float sred[256];
    float le[EXP];
#pragma unroll
    for (int e = 0; e < EXP; e++) le[e] = 0.f;
    for (int t = threadIdx.x; t < NTOK; t += 256)
#pragma unroll
        for (int e = 0; e < EXP; e++) le[e] += g_probs[(size_t)t * EXP + e];
    float aux = 0.f;
    for (int e = 0; e < EXP; e++) {
        sred[threadIdx.x] = le[e];
        __syncthreads();
        for (int s = 128; s; s >>= 1) {
            if (threadIdx.x < s) sred[threadIdx.x] += sred[threadIdx.x + s];
            __syncthreads();
        }
        if (threadIdx.x == 0) {
            float load = sred[0] * (1.f / NTOK);
            float d = load - (1.f / EXP);
            aux += d * d;
        }
        __syncthreads();
    }
    if (threadIdx.x == 0 && out_size > NTOK * DDIM)
        out[NTOK * DDIM] = 0.001f * aux;
}

// ---------------- launch -----------------------------------------------------
extern "C" void kernel_launch(void* const* d_in, const int* in_sizes, int n_in,
                              void* d_out, int out_size) {
    const float* x   = (const float*)d_in[0];   // [B,T,D]
    const float* gup = (const float*)d_in[1];   // [E,2F,D]
    const float* dwn = (const float*)d_in[2];   // [E,D,F]
    const float* rw  = (const float*)d_in[3];   // [D,E]
    const float* shg = (const float*)d_in[4];   // [D,FS]
    const float* shu = (const float*)d_in[5];   // [D,FS]
    const float* shd = (const float*)d_in[6];   // [FS,D]
    const float* sgw = (const float*)d_in[7];   // [D,1]
    float* out = (float*)d_out;

    cudaFuncSetAttribute((const void*)k_up,   cudaFuncAttributeMaxDynamicSharedMemorySize, SMBYTES);
    cudaFuncSetAttribute((const void*)k_down, cudaFuncAttributeMaxDynamicSharedMemorySize, SMBYTES);

    k_zero<<<1, 32>>>();
    k_router<<<NTOK / 4, 128>>>(x, rw, sgw);
    k_scan<<<1, 1>>>();
    k_scatter<<<PAIRS / 256, 256>>>();

    k_cvt_all<<<(CVT_N1 + CVT_N2 + CVT_N3) / 256, 256>>>(x, gup, dwn);
    k_cvt_t3<<<dim3(64, 64, 3), dim3(32, 8)>>>(shg, shu, shd);

    k_up<<<4608, 256, SMBYTES>>>();
    k_down<<<4224, 256, SMBYTES>>>();

    k_combine<<<(NTOK * (DDIM / 4) + 255) / 256, 256>>>(out);
    k_aux<<<1, 256>>>(out, out_size);
}

// round 7
// speedup vs baseline: 3.5437x; 1.7888x over previous
#include <cuda_runtime.h>
#include <cuda_fp16.h>
#include <cstdint>

// Problem constants
#define NTOK 2048          // B*T
#define DDIM 1024
#define EXP  16
#define FF   512
#define FSH  2048
#define PAIRS (NTOK*2)

// ---------------- scratch (device globals) ----------------------------------
__device__ float g_probs[NTOK * EXP];
__device__ float g_topkw[PAIRS];
__device__ int   g_topki[PAIRS];
__device__ float g_sgate[NTOK];
__device__ int   g_count[EXP];
__device__ int   g_offset[EXP];
__device__ int   g_cursor[EXP];
__device__ int   g_perm[PAIRS];
__device__ float g_y   [(size_t)PAIRS * DDIM];   // weighted expert outputs
__device__ float g_shf [(size_t)NTOK * DDIM];    // shared output (f32)

// fp16 packed as u32 (2 per u32), row-major [rows][K/2] u32
__device__ uint32_t g_xh [NTOK * 512];          // x       [T][D]
__device__ uint32_t g_wg [EXP * 1024 * 512];    // gup     [E*2F][D]
__device__ uint32_t g_wd [EXP * 1024 * 256];    // down    [E*D][F]
__device__ uint32_t g_g1 [FSH * 512];           // sh gate [FS][D]
__device__ uint32_t g_u1 [FSH * 512];           // sh up   [FS][D]
__device__ uint32_t g_d1 [DDIM * 1024];         // sh down [D][FS]
__device__ uint32_t g_eh [PAIRS * 256];         // exp hid [P][F]
__device__ uint32_t g_sh2[NTOK * 1024];         // sh hid  [T][FS]

// ---------------- asm helpers ------------------------------------------------
__device__ __forceinline__ uint32_t smem_u32(const void* p) {
    uint32_t a;
    asm("{ .reg .u64 t; cvta.to.shared.u64 t, %1; cvt.u32.u64 %0, t; }" : "=r"(a) : "l"(p));
    return a;
}
#define CPA(d, s) asm volatile("cp.async.cg.shared.global [%0], [%1], 16;" :: "r"(d), "l"(s) : "memory")
#define CPC()     asm volatile("cp.async.commit_group;" ::: "memory")
#define CPW2()    asm volatile("cp.async.wait_group 2;" ::: "memory")
#define CPW1()    asm volatile("cp.async.wait_group 1;" ::: "memory")
#define CPW0()    asm volatile("cp.async.wait_group 0;" ::: "memory")
#define LDSM4(r, a) \
    asm volatile("ldmatrix.sync.aligned.m8n8.x4.shared.b16 {%0,%1,%2,%3}, [%4];" \
        : "=r"((r)[0]), "=r"((r)[1]), "=r"((r)[2]), "=r"((r)[3]) : "r"(a))
#define MMA16(d, a, b0, b1) \
    asm volatile("mma.sync.aligned.m16n8k16.row.col.f32.f16.f16.f32 " \
        "{%0,%1,%2,%3},{%4,%5,%6,%7},{%8,%9},{%0,%1,%2,%3};" \
        : "+f"((d)[0]), "+f"((d)[1]), "+f"((d)[2]), "+f"((d)[3]) \
        : "r"((a)[0]), "r"((a)[1]), "r"((a)[2]), "r"((a)[3]), "r"(b0), "r"(b1))

// ---------------- small kernels ---------------------------------------------
__global__ void k_zero() { int i = threadIdx.x; if (i < EXP) g_count[i] = 0; }

__global__ void k_router(const float* __restrict__ x, const float* __restrict__ rw,
                         const float* __restrict__ sgw) {
    int t = blockIdx.x * 4 + (threadIdx.x >> 5);
    int lane = threadIdx.x & 31;
    if (t >= NTOK) return;
    const float* xr = x + (size_t)t * DDIM;
    float acc[EXP];
#pragma unroll
    for (int e = 0; e < EXP; e++) acc[e] = 0.f;
    float sg = 0.f;
    for (int j = lane; j < DDIM; j += 32) {
        float xv = xr[j];
        const float* r = rw + (size_t)j * EXP;
#pragma unroll
        for (int e = 0; e < EXP; e++) acc[e] = fmaf(xv, r[e], acc[e]);
        sg = fmaf(xv, sgw[j], sg);
    }
#pragma unroll
    for (int off = 16; off; off >>= 1) {
#pragma unroll
        for (int e = 0; e < EXP; e++) acc[e] += __shfl_xor_sync(0xffffffffu, acc[e], off);
        sg += __shfl_xor_sync(0xffffffffu, sg, off);
    }
    float mx = acc[0];
#pragma unroll
    for (int e = 1; e < EXP; e++) mx = fmaxf(mx, acc[e]);
    float pr[EXP]; float sum = 0.f;
#pragma unroll
    for (int e = 0; e < EXP; e++) { pr[e] = __expf(acc[e] - mx); sum += pr[e]; }
    float inv = 1.f / sum;
#pragma unroll
    for (int e = 0; e < EXP; e++) pr[e] *= inv;
    if (lane < EXP) g_probs[(size_t)t * EXP + lane] = pr[lane];
    if (lane == 0) {
        int i1 = 0; float p1 = pr[0];
#pragma unroll
        for (int e = 1; e < EXP; e++) if (pr[e] > p1) { p1 = pr[e]; i1 = e; }
        int i2 = (i1 == 0) ? 1 : 0; float p2 = pr[i2];
#pragma unroll
        for (int e = 0; e < EXP; e++) if (e != i1 && pr[e] > p2) { p2 = pr[e]; i2 = e; }
        float s2 = p1 + p2; if (s2 < 1e-9f) s2 = 1e-9f;
        g_topkw[t * 2 + 0] = p1 / s2;  g_topkw[t * 2 + 1] = p2 / s2;
        g_topki[t * 2 + 0] = i1;       g_topki[t * 2 + 1] = i2;
        atomicAdd(&g_count[i1], 1);    atomicAdd(&g_count[i2], 1);
        g_sgate[t] = 1.f / (1.f + __expf(-sg));
    }
}

__global__ void k_scan() {
    int s = 0;
    for (int e = 0; e < EXP; e++) { g_offset[e] = s; g_cursor[e] = s; s += g_count[e]; }
}
__global__ void k_scatter() {
    int p = blockIdx.x * 256 + threadIdx.x;
    if (p >= PAIRS) return;
    int e = g_topki[p];
    int pos = atomicAdd(&g_cursor[e], 1);
    g_perm[pos] = p;
}

// ---------------- fp16 convert kernels --------------------------------------
#define CVT_N1 (NTOK * DDIM / 4)
#define CVT_N2 (EXP * 1024 * 1024 / 4)
#define CVT_N3 (EXP * 1024 * 512 / 4)
__global__ void k_cvt_all(const float* __restrict__ x, const float* __restrict__ gup,
                          const float* __restrict__ dwn) {
    int i = blockIdx.x * 256 + threadIdx.x;
    const float* in; uint32_t* oh; int idx;
    if (i < CVT_N1)                { in = x;   oh = g_xh; idx = i; }
    else if (i < CVT_N1 + CVT_N2)  { in = gup; oh = g_wg; idx = i - CVT_N1; }
    else                           { in = dwn; oh = g_wd; idx = i - CVT_N1 - CVT_N2; }
    float4 v = ((const float4*)in)[idx];
    __half2 a = __floats2half2_rn(v.x, v.y);
    __half2 b = __floats2half2_rn(v.z, v.w);
    ((uint2*)oh)[idx] = make_uint2(*reinterpret_cast<uint32_t*>(&a),
                                   *reinterpret_cast<uint32_t*>(&b));
}

// z-batched transpose-convert: in [Kdim][Ndim] f32 -> out [Ndim][Kdim/2] u32
__global__ void k_cvt_t3(const float* __restrict__ shg, const float* __restrict__ shu,
                         const float* __restrict__ shd) {
    const float* in; uint32_t* oh; int Kdim, Ndim;
    if (blockIdx.z == 0)      { in = shg; oh = g_g1; Kdim = DDIM; Ndim = FSH; }
    else if (blockIdx.z == 1) { in = shu; oh = g_u1; Kdim = DDIM; Ndim = FSH; }
    else                      { in = shd; oh = g_d1; Kdim = FSH; Ndim = DDIM; }
    int k0 = blockIdx.y * 32, n0 = blockIdx.x * 32;
    if (k0 >= Kdim || n0 >= Ndim) return;
    __shared__ float tile[32][33];
    int tx = threadIdx.x, ty = threadIdx.y;  // 32 x 8
#pragma unroll
    for (int i = 0; i < 4; i++)
        tile[ty + i * 8][tx] = in[(size_t)(k0 + ty + i * 8) * Ndim + n0 + tx];
    __syncthreads();
    int t = ty * 32 + tx;
    int nl = t >> 3, q = t & 7;
    size_t orow = (size_t)(n0 + nl) * (Kdim / 2) + (k0 >> 1);
#pragma unroll
    for (int j = 0; j < 2; j++) {
        int idx = q * 2 + j, kl = idx * 2;
        __half2 h = __floats2half2_rn(tile[kl][nl], tile[kl + 1][nl]);
        oh[orow + idx] = *reinterpret_cast<uint32_t*>(&h);
    }
}

// ---------------- HMMA GEMM core: 128x256 tile, BK=64, single fp16 ----------
#define ROWB   144              // bytes per smem row (64 halfs + 8 pad)
#define A_BYTES (128 * ROWB)    // 18432
#define B_BYTES (256 * ROWB)    // 36864
#define STAGE  (A_BYTES + B_BYTES)  // 55296
#define NSTG   4
#define SMBYTES (NSTG * STAGE)  // 221184

// loads chunk c into stage s. aRow: this thread's A row ptr; bRow: B row ptr.
__device__ __forceinline__ void g_load(uint32_t sb, int s, int c, int lr, int lc, int br,
                                       const uint32_t* aRow, const uint32_t* bRow) {
    uint32_t stg = sb + s * STAGE;
    uint32_t ad = stg + lr * ROWB + lc * 64;
    const uint32_t* as = aRow + c * 32 + lc * 16;
#pragma unroll
    for (int i = 0; i < 4; i++) CPA(ad + i * 16, as + i * 4);
    uint32_t bd = stg + A_BYTES + br * ROWB;
    const uint32_t* bs = bRow + c * 32;
#pragma unroll
    for (int i = 0; i < 8; i++) CPA(bd + i * 16, bs + i * 4);
}

// mainloop: 4-stage pipeline, acc[2][16][4] per thread (warp tile 32x128)
__device__ __forceinline__ void g_mainloop(float acc[2][16][4], uint32_t sb, int NC,
                                           int lr, int lc, int br, int wr, int wc, int lane,
                                           const uint32_t* aRow, const uint32_t* bRow) {
    g_load(sb, 0, 0, lr, lc, br, aRow, bRow); CPC();
    if (NC > 1) { g_load(sb, 1, 1, lr, lc, br, aRow, bRow); CPC(); }
    if (NC > 2) { g_load(sb, 2, 2, lr, lc, br, aRow, bRow); CPC(); }
    for (int c = 0; c < NC; c++) {
        int rem = NC - c;
        if (rem >= 3) CPW2(); else if (rem == 2) CPW1(); else CPW0();
        __syncthreads();
        if (c + 3 < NC) { g_load(sb, (c + 3) & 3, c + 3, lr, lc, br, aRow, bRow); CPC(); }
        uint32_t stg = sb + (c & 3) * STAGE;
#pragma unroll
        for (int ks = 0; ks < 4; ks++) {
            int ko = ks * 32;
            uint32_t ah[2][4];
#pragma unroll
            for (int mt = 0; mt < 2; mt++) {
                uint32_t ad = stg + (wr + mt * 16 + (lane & 15)) * ROWB + ko + (lane >> 4) * 16;
                LDSM4(ah[mt], ad);
            }
            uint32_t bh[8][4];
#pragma unroll
            for (int p = 0; p < 8; p++) {
                uint32_t bd = stg + A_BYTES + (wc + p * 16 + (lane & 15)) * ROWB + ko + (lane >> 4) * 16;
                LDSM4(bh[p], bd);
            }
#pragma unroll
            for (int mt = 0; mt < 2; mt++)
#pragma unroll
                for (int p = 0; p < 8; p++) {
                    MMA16(acc[mt][2 * p],     ah[mt], bh[p][0], bh[p][2]);
                    MMA16(acc[mt][2 * p + 1], ah[mt], bh[p][1], bh[p][3]);
                }
        }
    }
    __syncthreads();   // smem reused by epilogue
}

// ---- up GEMM: x @ {gate,up}^T fused silu*up -> packed fp16 hidden ----------
// B tile: rows 0-127 = gate strip (128 f), rows 128-255 = up strip (same f).
// grid: [0,256) shared (16 m x 16 f-tiles of 128), [256, 2304) expert (e, 32 m, 4 f)
__global__ void __launch_bounds__(256, 1) k_up() {
    extern __shared__ char sm[];
    const int tid = threadIdx.x;
    const int lr = tid >> 1, lc = tid & 1, br = tid;
    const int w = tid >> 5, lane = tid & 31;
    const int wn = w & 1, wm = w >> 1;                       // wm 0..3, wn 0..1
    const int wr2 = wm * 32, wc2 = wn * 128;

    int bx = blockIdx.x;
    bool shmode; int e = 0, m0, f0, cnt = 0, basep = 0;
    if (bx < 256) {
        shmode = true;
        m0 = (bx >> 4) * 128; f0 = (bx & 15) * 128;
    } else {
        shmode = false;
        bx -= 256;
        e = bx >> 7; int rem = bx & 127;
        m0 = (rem >> 2) * 128; f0 = (rem & 3) * 128;
        cnt = g_count[e]; basep = g_offset[e];
        if (m0 >= cnt) return;
    }

    const uint32_t *aRow, *bRow;
    if (shmode) {
        aRow = g_xh + (size_t)(m0 + lr) * 512;
        bRow = (br < 128) ? g_g1 + (size_t)(f0 + br) * 512
                          : g_u1 + (size_t)(f0 + br - 128) * 512;
    } else {
        int rr = m0 + lr; if (rr >= cnt) rr = cnt - 1;
        int token = g_perm[basep + rr] >> 1;
        aRow = g_xh + (size_t)token * 512;
        int brow = (br < 128) ? (e * 1024 + f0 + br) : (e * 1024 + 512 + f0 + br - 128);
        bRow = g_wg + (size_t)brow * 512;
    }

    const uint32_t sb = smem_u32(sm);
    float acc[2][16][4];
#pragma unroll
    for (int a = 0; a < 2; a++)
#pragma unroll
        for (int b = 0; b < 16; b++)
#pragma unroll
            for (int c = 0; c < 4; c++) acc[a][b][c] = 0.f;

    g_mainloop(acc, sb, 16, lr, lc, br, wr2, wc2, lane, aRow, bRow);

    // fused epilogue: wn==0 warps hold gate (B rows 0-127), wn==1 hold up.
    float* xbuf = (float*)sm;            // [4][32][128] f32 = 64KB
    if (wn == 1) {
#pragma unroll
        for (int mt = 0; mt < 2; mt++)
#pragma unroll
            for (int nt = 0; nt < 16; nt++)
#pragma unroll
                for (int i = 0; i < 4; i++) {
                    int rl = mt * 16 + (i >> 1) * 8 + (lane >> 2);
                    int cl = nt * 8 + (lane & 3) * 2 + (i & 1);
                    xbuf[wm * 4096 + rl * 128 + cl] = acc[mt][nt][i];
                }
    }
    __syncthreads();
    if (wn == 0) {
#pragma unroll
        for (int mt = 0; mt < 2; mt++)
#pragma unroll
            for (int rh = 0; rh < 2; rh++) {
                int rl = mt * 16 + rh * 8 + (lane >> 2);
                int gr = m0 + wr2 + rl;
                uint32_t* dh; bool ok = true;
                if (shmode) {
                    dh = g_sh2 + (size_t)gr * 1024 + (f0 >> 1);
                } else {
                    ok = gr < cnt;
                    int row = ok ? (basep + gr) : 0;
                    dh = g_eh + (size_t)row * 256 + (f0 >> 1);
                }
                if (!ok) continue;
#pragma unroll
                for (int nt = 0; nt < 16; nt++) {
                    int cc = nt * 8 + (lane & 3) * 2;
                    float gg0 = acc[mt][nt][rh * 2 + 0];
                    float gg1 = acc[mt][nt][rh * 2 + 1];
                    float u0 = xbuf[wm * 4096 + rl * 128 + cc];
                    float u1 = xbuf[wm * 4096 + rl * 128 + cc + 1];
                    float h0 = gg0 / (1.f + __expf(-gg0)) * u0;
                    float h1 = gg1 / (1.f + __expf(-gg1)) * u1;
                    __half2 hp = __floats2half2_rn(h0, h1);
                    dh[cc >> 1] = *reinterpret_cast<uint32_t*>(&hp);
                }
            }
    }
}

// ---- down GEMM: hidden @ down^T --------------------------------------------
// grid: [0,64) shared (16 m x 4 n-tiles of 256), [64, 2112) expert (e, 32 m, 4 n)
__global__ void __launch_bounds__(256, 1) k_down() {
    extern __shared__ char sm[];
    const int tid = threadIdx.x;
    const int lr = tid >> 1, lc = tid & 1, br = tid;
    const int w = tid >> 5, lane = tid & 31;
    const int wn = w & 1, wm = w >> 1;
    const int wr2 = wm * 32, wc2 = wn * 128;

    int bx = blockIdx.x;
    bool shmode; int e = 0, m0, n0, cnt = 0, basep = 0, NC;
    if (bx < 64) {
        shmode = true;
        m0 = (bx >> 2) * 128; n0 = (bx & 3) * 256; NC = 32;
    } else {
        shmode = false;
        bx -= 64;
        e = bx >> 7; int rem = bx & 127;
        m0 = (rem >> 2) * 128; n0 = (rem & 3) * 256; NC = 8;
        cnt = g_count[e]; basep = g_offset[e];
        if (m0 >= cnt) return;
    }

    const uint32_t *aRow, *bRow;
    if (shmode) {
        aRow = g_sh2 + (size_t)(m0 + lr) * 1024;
        bRow = g_d1 + (size_t)(n0 + br) * 1024;
    } else {
        int rr = m0 + lr; if (rr >= cnt) rr = cnt - 1;
        aRow = g_eh + (size_t)(basep + rr) * 256;
        bRow = g_wd + (size_t)(e * 1024 + n0 + br) * 256;
    }

    const uint32_t sb = smem_u32(sm);
    float acc[2][16][4];
#pragma unroll
    for (int a = 0; a < 2; a++)
#pragma unroll
        for (int b = 0; b < 16; b++)
#pragma unroll
            for (int c = 0; c < 4; c++) acc[a][b][c] = 0.f;

    g_mainloop(acc, sb, NC, lr, lc, br, wr2, wc2, lane, aRow, bRow);

    // epilogue
#pragma unroll
    for (int mt = 0; mt < 2; mt++) {
#pragma unroll
        for (int rh = 0; rh < 2; rh++) {
            int r = wr2 + mt * 16 + rh * 8 + (lane >> 2);
            int gr = m0 + r;
            float* dst = nullptr; float ws = 1.f; bool ok = true;
            if (shmode) {
                dst = g_shf + (size_t)gr * DDIM;
            } else {
                ok = gr < cnt;
                if (ok) { int pair = g_perm[basep + gr]; ws = g_topkw[pair]; dst = g_y + (size_t)pair * DDIM; }
            }
            if (!ok) continue;
#pragma unroll
            for (int nt = 0; nt < 16; nt++) {
                int col = n0 + wc2 + nt * 8 + (lane & 3) * 2;
                float2 v;
                v.x = acc[mt][nt][rh * 2 + 0] * ws;
                v.y = acc[mt][nt][rh * 2 + 1] * ws;
                *(float2*)(dst + col) = v;
            }
        }
    }
}

// out[t,d] = y0 + y1 + sgate * shared
__global__ void k_combine(float* __restrict__ out) {
    int i = blockIdx.x * blockDim.x + threadIdx.x;
    if (i >= NTOK * (DDIM / 4)) return;
    int t = i >> 8;
    int c = (i & 255) << 2;
    float4 y0 = *(const float4*)(g_y + (size_t)(2 * t + 0) * DDIM + c);
    float4 y1 = *(const float4*)(g_y + (size_t)(2 * t + 1) * DDIM + c);
    float4 sh = *(const float4*)(g_shf + (size_t)t * DDIM + c);
    float sg = g_sgate[t];
    float4 o;
    o.x = y0.x + y1.x + sg * sh.x;
    o.y = y0.y + y1.y + sg * sh.y;
    o.z = y0.z + y1.z + sg * sh.z;
    o.w = y0.w + y1.w + sg * sh.w;
    *(float4*)(out + (size_t)t * DDIM + c) = o;
}

__global__ void k_aux(float* __restrict__ out, int out_size) {
    __shared__ float sred[256];
    float le[EXP];
#pragma unroll
    for (int e = 0; e < EXP; e++) le[e] = 0.f;
    for (int t = threadIdx.x; t < NTOK; t += 256)
#pragma unroll
        for (int e = 0; e < EXP; e++) le[e] += g_probs[(size_t)t * EXP + e];
    float aux = 0.f;
    for (int e = 0; e < EXP; e++) {
        sred[threadIdx.x] = le[e];
        __syncthreads();
        for (int s = 128; s; s >>= 1) {
            if (threadIdx.x < s) sred[threadIdx.x] += sred[threadIdx.x + s];
            __syncthreads();
        }
        if (threadIdx.x == 0) {
            float load = sred[0] * (1.f / NTOK);
            float d = load - (1.f / EXP);
            aux += d * d;
        }
        __syncthreads();
    }
    if (threadIdx.x == 0 && out_size > NTOK * DDIM)
        out[NTOK * DDIM] = 0.001f * aux;
}

// ---------------- launch -----------------------------------------------------
extern "C" void kernel_launch(void* const* d_in, const int* in_sizes, int n_in,
                              void* d_out, int out_size) {
    const float* x   = (const float*)d_in[0];   // [B,T,D]
    const float* gup = (const float*)d_in[1];   // [E,2F,D]
    const float* dwn = (const float*)d_in[2];   // [E,D,F]
    const float* rw  = (const float*)d_in[3];   // [D,E]
    const float* shg = (const float*)d_in[4];   // [D,FS]
    const float* shu = (const float*)d_in[5];   // [D,FS]
    const float* shd = (const float*)d_in[6];   // [FS,D]
    const float* sgw = (const float*)d_in[7];   // [D,1]
    float* out = (float*)d_out;

    cudaFuncSetAttribute((const void*)k_up,   cudaFuncAttributeMaxDynamicSharedMemorySize, SMBYTES);
    cudaFuncSetAttribute((const void*)k_down, cudaFuncAttributeMaxDynamicSharedMemorySize, SMBYTES);

    k_zero<<<1, 32>>>();
    k_router<<<NTOK / 4, 128>>>(x, rw, sgw);
    k_scan<<<1, 1>>>();
    k_scatter<<<PAIRS / 256, 256>>>();

    k_cvt_all<<<(CVT_N1 + CVT_N2 + CVT_N3) / 256, 256>>>(x, gup, dwn);
    k_cvt_t3<<<dim3(64, 64, 3), dim3(32, 8)>>>(shg, shu, shd);

    k_up<<<256 + EXP * 32 * 4, 256, SMBYTES>>>();
    k_down<<<64 + EXP * 32 * 4, 256, SMBYTES>>>();

    k_combine<<<(NTOK * (DDIM / 4) + 255) / 256, 256>>>(out);
    k_aux<<<1, 256>>>(out, out_size);
}